// round 13
// baseline (speedup 1.0000x reference)
#include <cuda_runtime.h>
#include <cstdint>
#include <math.h>

#define BATCH   2048
#define IN_DIM  512
#define NUM_OUT 256

#define BM 64
#define BN 128
#define BK 16
#define NTHREADS 128
#define KSPLIT 4
#define KCHUNK (IN_DIM / KSPLIT)    // 128
#define NSTEPS (KCHUNK / BK)        // 8

typedef unsigned long long ull;

// g_w[k][o] = -sigmoid(5 * W_raw[o][k]); [512][256] floats, 512 KB.
__device__ float g_w[IN_DIM * NUM_OUT];
// Partial products per K-chunk: 8 MB
__device__ float g_part[KSPLIT][BATCH * NUM_OUT];

// Coalesced transpose precompute (R6-measured): load W[o][k] coalesced along k,
// store g_w[k][o] coalesced along o, sigmoid applied on the way out.
__global__ void precompute_kernel(const float* __restrict__ Wraw) {
    __shared__ float t[32][33];
    const int o0 = blockIdx.x * 32;
    const int k0 = blockIdx.y * 32;
    const int tx = threadIdx.x;      // 0..31
    const int ty = threadIdx.y;      // 0..7
#pragma unroll
    for (int j = 0; j < 32; j += 8)
        t[ty + j][tx] = Wraw[(o0 + ty + j) * IN_DIM + k0 + tx];
    __syncthreads();
#pragma unroll
    for (int j = 0; j < 32; j += 8) {
        float v = t[tx][ty + j];     // = W[o0+tx][k0+ty+j]
        float w = 1.0f / (1.0f + __expf(-5.0f * v));
        g_w[(k0 + ty + j) * NUM_OUT + o0 + tx] = -w;
    }
}

__device__ __forceinline__ ull ffma2(ull a, ull b, ull c) {
    ull d;
    asm("fma.rn.f32x2 %0, %1, %2, %3;" : "=l"(d) : "l"(a), "l"(b), "l"(c));
    return d;
}
__device__ __forceinline__ ull fmul2(ull a, ull b) {
    ull d;
    asm("mul.rn.f32x2 %0, %1, %2;" : "=l"(d) : "l"(a), "l"(b));
    return d;
}
__device__ __forceinline__ void cp_async16(uint32_t smem, const void* gptr) {
    asm volatile("cp.async.cg.shared.global [%0], [%1], 16;" :: "r"(smem), "l"(gptr));
}

// Self-contained x-duplication store: xs[b][kb+slot][2*xm] = (1-val, 1-val)
#define XDUP(b, slot, val) do {                                            \
    float2 _p; _p.x = 1.0f - (val); _p.y = _p.x;                           \
    *reinterpret_cast<float2*>(&xs[b][kb + (slot)][2 * xm]) = _p;          \
} while (0)

// 64(M) x 128(N) tile per CTA over one 128-K chunk. Thread tile 8x8.
// Accumulator packs two adjacent N-cols per f32x2 (no w duplication).
// x stored duplicated in smem: xs[k][2*row] = xs[k][2*row+1] = 1-x.
// w row piece-permuted: 16B piece p -> phys chunk (p even ? p/2 : 16+p/2),
// so each thread's two LDS.128 hit contiguous 256B halves (conflict-free).
// Inner update: p = (-w)*t (2 reg-pairs, rt2), acc = acc*p + acc (acc twice
// in one instr -> 2 distinct pairs, rt2). Avoids the rt=3 RF-bank penalty of
// the 3-distinct-pair ffma2(w, x, ONE2) form.
__global__ void __launch_bounds__(NTHREADS, 2)
logic_kernel(const float* __restrict__ x) {
    __shared__ __align__(16) float xs[2][BK][2 * BM + 4];   // 132 floats/row
    __shared__ __align__(16) float ws[2][BK][BN + 4];       // 132 floats/row

    const int tid = threadIdx.x;
    const int bm0 = blockIdx.x * BM;
    const int bn  = blockIdx.y;          // 0..1
    const int kz  = blockIdx.z;          // K-chunk
    const int kbase = kz * KCHUNK;

    const int cg = tid & 15;   // col-group: 8 cols each
    const int rg = tid >> 4;   // row-group: 8 rows each

    // x staging: row xm (0..63), k-half xq (8 k's each)
    const int xm = tid & 63;
    const int xq = tid >> 6;   // 0 or 1
    const int kb = xq * 8;

    const ull ONE2 = 0x3F8000003F800000ULL;
    ull acc[8][4];
#pragma unroll
    for (int i = 0; i < 8; ++i)
#pragma unroll
        for (int j = 0; j < 4; ++j) acc[i][j] = ONE2;

    const float* xrow = x + (ull)(bm0 + xm) * IN_DIM + kbase + xq * 8;

    // ---------------- prologue: fill buffer 0 ----------------
    {
        float4 a = *reinterpret_cast<const float4*>(xrow + 0);
        float4 b = *reinterpret_cast<const float4*>(xrow + 4);
#pragma unroll
        for (int c = 0; c < 4; ++c) {
            int idx = c * 128 + tid;
            int k   = idx >> 5;        // 0..15
            int q   = idx & 31;        // 16B chunk within row
            int goff = ((q & 15) * 8 + (q >> 4) * 4);
            const float* src = g_w + (ull)(kbase + k) * NUM_OUT + bn * BN + goff;
            cp_async16((uint32_t)__cvta_generic_to_shared(&ws[0][k][q * 4]), src);
        }
        asm volatile("cp.async.commit_group;" ::: "memory");
        XDUP(0, 0, a.x); XDUP(0, 1, a.y); XDUP(0, 2, a.z); XDUP(0, 3, a.w);
        XDUP(0, 4, b.x); XDUP(0, 5, b.y); XDUP(0, 6, b.z); XDUP(0, 7, b.w);
    }

    // ---------------- main loop ----------------
    for (int step = 0; step < NSTEPS; ++step) {
        const int buf  = step & 1;
        const int nbuf = buf ^ 1;
        const bool more = (step + 1 < NSTEPS);

        __syncthreads();   // compute(step-1) done; x STS(step) visible

        float4 a, b;
        if (more) {
            const float* xp = xrow + (step + 1) * BK;
            a = *reinterpret_cast<const float4*>(xp + 0);
            b = *reinterpret_cast<const float4*>(xp + 4);
            int k0 = kbase + (step + 1) * BK;
#pragma unroll
            for (int c = 0; c < 4; ++c) {
                int idx = c * 128 + tid;
                int k   = idx >> 5;
                int q   = idx & 31;
                int goff = ((q & 15) * 8 + (q >> 4) * 4);
                const float* src = g_w + (ull)(k0 + k) * NUM_OUT + bn * BN + goff;
                cp_async16((uint32_t)__cvta_generic_to_shared(&ws[nbuf][k][q * 4]), src);
            }
        }
        asm volatile("cp.async.commit_group;" ::: "memory");
        asm volatile("cp.async.wait_group 1;" ::: "memory");
        __syncthreads();   // ws[buf] fully landed

        // ---------- compute on buf (register-pipelined LDS) ----------
        ull xv[2][8], wv[2][4];
#define LDK(kk, ph) do {                                                         \
        ulonglong2 xa = *reinterpret_cast<const ulonglong2*>(&xs[buf][kk][rg * 16]);      \
        ulonglong2 xb = *reinterpret_cast<const ulonglong2*>(&xs[buf][kk][rg * 16 + 4]);  \
        ulonglong2 xc = *reinterpret_cast<const ulonglong2*>(&xs[buf][kk][rg * 16 + 8]);  \
        ulonglong2 xd = *reinterpret_cast<const ulonglong2*>(&xs[buf][kk][rg * 16 + 12]); \
        ulonglong2 wa = *reinterpret_cast<const ulonglong2*>(&ws[buf][kk][cg * 4]);       \
        ulonglong2 wb = *reinterpret_cast<const ulonglong2*>(&ws[buf][kk][64 + cg * 4]);  \
        xv[ph][0] = xa.x; xv[ph][1] = xa.y; xv[ph][2] = xb.x; xv[ph][3] = xb.y;  \
        xv[ph][4] = xc.x; xv[ph][5] = xc.y; xv[ph][6] = xd.x; xv[ph][7] = xd.y;  \
        wv[ph][0] = wa.x; wv[ph][1] = wa.y; wv[ph][2] = wb.x; wv[ph][3] = wb.y;  \
    } while (0)

        LDK(0, 0);
#pragma unroll
        for (int k = 0; k < BK; ++k) {
            const int ph  = k & 1;
            const int nph = ph ^ 1;
            if (k + 1 < BK) LDK(k + 1, nph);   // prefetch next k's operands
#pragma unroll
            for (int i = 0; i < 8; ++i) {
#pragma unroll
                for (int j = 0; j < 4; ++j) {
                    ull p = fmul2(wv[ph][j], xv[ph][i]);          // (-w)*t
                    acc[i][j] = ffma2(acc[i][j], p, acc[i][j]);   // acc*(1-w*t)
                }
            }
        }
#undef LDK

        if (more) {
            XDUP(nbuf, 0, a.x); XDUP(nbuf, 1, a.y); XDUP(nbuf, 2, a.z); XDUP(nbuf, 3, a.w);
            XDUP(nbuf, 4, b.x); XDUP(nbuf, 5, b.y); XDUP(nbuf, 6, b.z); XDUP(nbuf, 7, b.w);
        }
    }

    // ---------------- epilogue: write partial products ----------------
    float* prow = g_part[kz] + (ull)(bm0 + rg * 8) * NUM_OUT + bn * BN + cg * 8;
#pragma unroll
    for (int i = 0; i < 8; ++i) {
        float4 v0, v1;
        v0.x = __uint_as_float((unsigned)(acc[i][0]));
        v0.y = __uint_as_float((unsigned)(acc[i][0] >> 32));
        v0.z = __uint_as_float((unsigned)(acc[i][1]));
        v0.w = __uint_as_float((unsigned)(acc[i][1] >> 32));
        v1.x = __uint_as_float((unsigned)(acc[i][2]));
        v1.y = __uint_as_float((unsigned)(acc[i][2] >> 32));
        v1.z = __uint_as_float((unsigned)(acc[i][3]));
        v1.w = __uint_as_float((unsigned)(acc[i][3] >> 32));
        *reinterpret_cast<float4*>(prow + (ull)i * NUM_OUT)     = v0;
        *reinterpret_cast<float4*>(prow + (ull)i * NUM_OUT + 4) = v1;
    }
}

// out = p0 * p1 * p2 * p3 elementwise (float4-vectorized)
__global__ void combine_kernel(float* __restrict__ out) {
    int i = blockIdx.x * blockDim.x + threadIdx.x;
    if (i < (BATCH * NUM_OUT) / 4) {
        float4 a = reinterpret_cast<const float4*>(g_part[0])[i];
        float4 b = reinterpret_cast<const float4*>(g_part[1])[i];
        float4 c = reinterpret_cast<const float4*>(g_part[2])[i];
        float4 d = reinterpret_cast<const float4*>(g_part[3])[i];
        float4 v;
        v.x = (a.x * b.x) * (c.x * d.x);
        v.y = (a.y * b.y) * (c.y * d.y);
        v.z = (a.z * b.z) * (c.z * d.z);
        v.w = (a.w * b.w) * (c.w * d.w);
        reinterpret_cast<float4*>(out)[i] = v;
    }
}

extern "C" void kernel_launch(void* const* d_in, const int* in_sizes, int n_in,
                              void* d_out, int out_size) {
    const float* x    = (const float*)d_in[0];   // [2048, 512]
    const float* Wraw = (const float*)d_in[1];   // [256, 512]
    float* out        = (float*)d_out;           // [2048, 256]

    dim3 pgrid(NUM_OUT / 32, IN_DIM / 32);       // 8 x 16
    dim3 pblk(32, 8);
    precompute_kernel<<<pgrid, pblk>>>(Wraw);

    dim3 grid(BATCH / BM, NUM_OUT / BN, KSPLIT); // 32 x 2 x 4 = 256 CTAs
    logic_kernel<<<grid, NTHREADS>>>(x);

    combine_kernel<<<(BATCH * NUM_OUT / 4 + 255) / 256, 256>>>(out);
}

// round 15
// speedup vs baseline: 1.0018x; 1.0018x over previous
#include <cuda_runtime.h>
#include <cstdint>
#include <math.h>

#define BATCH   2048
#define IN_DIM  512
#define NUM_OUT 256

#define BM 64
#define BN 128
#define BK 16
#define NTHREADS 128
#define KSPLIT 4
#define KCHUNK (IN_DIM / KSPLIT)    // 128
#define NSTEPS (KCHUNK / BK)        // 8

typedef unsigned long long ull;

// g_w[k][o] = -sigmoid(5 * W_raw[o][k]); [512][256] floats, 512 KB.
__device__ float g_w[IN_DIM * NUM_OUT];
// Partial products per K-chunk: 8 MB
__device__ float g_part[KSPLIT][BATCH * NUM_OUT];

// Coalesced transpose precompute (R6-measured): load W[o][k] coalesced along k,
// store g_w[k][o] coalesced along o, sigmoid applied on the way out.
__global__ void precompute_kernel(const float* __restrict__ Wraw) {
    __shared__ float t[32][33];
    const int o0 = blockIdx.x * 32;
    const int k0 = blockIdx.y * 32;
    const int tx = threadIdx.x;      // 0..31
    const int ty = threadIdx.y;      // 0..7
#pragma unroll
    for (int j = 0; j < 32; j += 8)
        t[ty + j][tx] = Wraw[(o0 + ty + j) * IN_DIM + k0 + tx];
    __syncthreads();
#pragma unroll
    for (int j = 0; j < 32; j += 8) {
        float v = t[tx][ty + j];     // = W[o0+tx][k0+ty+j]
        float w = 1.0f / (1.0f + __expf(-5.0f * v));
        g_w[(k0 + ty + j) * NUM_OUT + o0 + tx] = -w;
    }
}

__device__ __forceinline__ ull ffma2(ull a, ull b, ull c) {
    ull d;
    asm("fma.rn.f32x2 %0, %1, %2, %3;" : "=l"(d) : "l"(a), "l"(b), "l"(c));
    return d;
}
__device__ __forceinline__ ull fmul2(ull a, ull b) {
    ull d;
    asm("mul.rn.f32x2 %0, %1, %2;" : "=l"(d) : "l"(a), "l"(b));
    return d;
}
__device__ __forceinline__ void cp_async16(uint32_t smem, const void* gptr) {
    asm volatile("cp.async.cg.shared.global [%0], [%1], 16;" :: "r"(smem), "l"(gptr));
}

// Self-contained x-duplication store: xs[b][kb+slot][2*xm] = (1-val, 1-val)
#define XDUP(b, slot, val) do {                                            \
    float2 _p; _p.x = 1.0f - (val); _p.y = _p.x;                           \
    *reinterpret_cast<float2*>(&xs[b][kb + (slot)][2 * xm]) = _p;          \
} while (0)

// 64(M) x 128(N) tile per CTA over one 128-K chunk. Thread tile 8x8.
// Accumulator packs two adjacent N-cols per f32x2 (no w duplication).
// x stored duplicated in smem: xs[k][2*row] = xs[k][2*row+1] = 1-x.
// w row piece-permuted: 16B piece p -> phys chunk (p even ? p/2 : 16+p/2),
// so each thread's two LDS.128 hit contiguous 256B halves (conflict-free).
// Inner update: p = (-w)*t (2 reg-pairs, rt2), acc = acc*p + acc (acc twice
// in one instr -> 2 distinct pairs, rt2). Avoids the rt=3 RF-bank penalty of
// the 3-distinct-pair ffma2(w, x, ONE2) form.
__global__ void __launch_bounds__(NTHREADS, 2)
logic_kernel(const float* __restrict__ x) {
    __shared__ __align__(16) float xs[2][BK][2 * BM + 4];   // 132 floats/row
    __shared__ __align__(16) float ws[2][BK][BN + 4];       // 132 floats/row

    const int tid = threadIdx.x;
    const int bm0 = blockIdx.x * BM;
    const int bn  = blockIdx.y;          // 0..1
    const int kz  = blockIdx.z;          // K-chunk
    const int kbase = kz * KCHUNK;

    const int cg = tid & 15;   // col-group: 8 cols each
    const int rg = tid >> 4;   // row-group: 8 rows each

    // x staging: row xm (0..63), k-half xq (8 k's each)
    const int xm = tid & 63;
    const int xq = tid >> 6;   // 0 or 1
    const int kb = xq * 8;

    const ull ONE2 = 0x3F8000003F800000ULL;
    ull acc[8][4];
#pragma unroll
    for (int i = 0; i < 8; ++i)
#pragma unroll
        for (int j = 0; j < 4; ++j) acc[i][j] = ONE2;

    const float* xrow = x + (ull)(bm0 + xm) * IN_DIM + kbase + xq * 8;

    // ---------------- prologue: fill buffer 0 ----------------
    {
        float4 a = *reinterpret_cast<const float4*>(xrow + 0);
        float4 b = *reinterpret_cast<const float4*>(xrow + 4);
#pragma unroll
        for (int c = 0; c < 4; ++c) {
            int idx = c * 128 + tid;
            int k   = idx >> 5;        // 0..15
            int q   = idx & 31;        // 16B chunk within row
            int goff = ((q & 15) * 8 + (q >> 4) * 4);
            const float* src = g_w + (ull)(kbase + k) * NUM_OUT + bn * BN + goff;
            cp_async16((uint32_t)__cvta_generic_to_shared(&ws[0][k][q * 4]), src);
        }
        asm volatile("cp.async.commit_group;" ::: "memory");
        XDUP(0, 0, a.x); XDUP(0, 1, a.y); XDUP(0, 2, a.z); XDUP(0, 3, a.w);
        XDUP(0, 4, b.x); XDUP(0, 5, b.y); XDUP(0, 6, b.z); XDUP(0, 7, b.w);
    }

    // ---------------- main loop ----------------
    for (int step = 0; step < NSTEPS; ++step) {
        const int buf  = step & 1;
        const int nbuf = buf ^ 1;
        const bool more = (step + 1 < NSTEPS);

        __syncthreads();   // compute(step-1) done; x STS(step) visible

        float4 a, b;
        if (more) {
            const float* xp = xrow + (step + 1) * BK;
            a = *reinterpret_cast<const float4*>(xp + 0);
            b = *reinterpret_cast<const float4*>(xp + 4);
            int k0 = kbase + (step + 1) * BK;
#pragma unroll
            for (int c = 0; c < 4; ++c) {
                int idx = c * 128 + tid;
                int k   = idx >> 5;
                int q   = idx & 31;
                int goff = ((q & 15) * 8 + (q >> 4) * 4);
                const float* src = g_w + (ull)(k0 + k) * NUM_OUT + bn * BN + goff;
                cp_async16((uint32_t)__cvta_generic_to_shared(&ws[nbuf][k][q * 4]), src);
            }
        }
        asm volatile("cp.async.commit_group;" ::: "memory");
        asm volatile("cp.async.wait_group 1;" ::: "memory");
        __syncthreads();   // ws[buf] fully landed

        // ---------- compute on buf (register-pipelined LDS) ----------
        ull xv[2][8], wv[2][4];
#define LDK(kk, ph) do {                                                         \
        ulonglong2 xa = *reinterpret_cast<const ulonglong2*>(&xs[buf][kk][rg * 16]);      \
        ulonglong2 xb = *reinterpret_cast<const ulonglong2*>(&xs[buf][kk][rg * 16 + 4]);  \
        ulonglong2 xc = *reinterpret_cast<const ulonglong2*>(&xs[buf][kk][rg * 16 + 8]);  \
        ulonglong2 xd = *reinterpret_cast<const ulonglong2*>(&xs[buf][kk][rg * 16 + 12]); \
        ulonglong2 wa = *reinterpret_cast<const ulonglong2*>(&ws[buf][kk][cg * 4]);       \
        ulonglong2 wb = *reinterpret_cast<const ulonglong2*>(&ws[buf][kk][64 + cg * 4]);  \
        xv[ph][0] = xa.x; xv[ph][1] = xa.y; xv[ph][2] = xb.x; xv[ph][3] = xb.y;  \
        xv[ph][4] = xc.x; xv[ph][5] = xc.y; xv[ph][6] = xd.x; xv[ph][7] = xd.y;  \
        wv[ph][0] = wa.x; wv[ph][1] = wa.y; wv[ph][2] = wb.x; wv[ph][3] = wb.y;  \
    } while (0)

        LDK(0, 0);
#pragma unroll
        for (int k = 0; k < BK; ++k) {
            const int ph  = k & 1;
            const int nph = ph ^ 1;
            if (k + 1 < BK) LDK(k + 1, nph);   // prefetch next k's operands
#pragma unroll
            for (int i = 0; i < 8; ++i) {
#pragma unroll
                for (int j = 0; j < 4; ++j) {
                    ull p = fmul2(wv[ph][j], xv[ph][i]);          // (-w)*t
                    acc[i][j] = ffma2(acc[i][j], p, acc[i][j]);   // acc*(1-w*t)
                }
            }
        }
#undef LDK

        if (more) {
            XDUP(nbuf, 0, a.x); XDUP(nbuf, 1, a.y); XDUP(nbuf, 2, a.z); XDUP(nbuf, 3, a.w);
            XDUP(nbuf, 4, b.x); XDUP(nbuf, 5, b.y); XDUP(nbuf, 6, b.z); XDUP(nbuf, 7, b.w);
        }
    }

    // ---------------- epilogue: write partial products ----------------
    float* prow = g_part[kz] + (ull)(bm0 + rg * 8) * NUM_OUT + bn * BN + cg * 8;
#pragma unroll
    for (int i = 0; i < 8; ++i) {
        float4 v0, v1;
        v0.x = __uint_as_float((unsigned)(acc[i][0]));
        v0.y = __uint_as_float((unsigned)(acc[i][0] >> 32));
        v0.z = __uint_as_float((unsigned)(acc[i][1]));
        v0.w = __uint_as_float((unsigned)(acc[i][1] >> 32));
        v1.x = __uint_as_float((unsigned)(acc[i][2]));
        v1.y = __uint_as_float((unsigned)(acc[i][2] >> 32));
        v1.z = __uint_as_float((unsigned)(acc[i][3]));
        v1.w = __uint_as_float((unsigned)(acc[i][3] >> 32));
        *reinterpret_cast<float4*>(prow + (ull)i * NUM_OUT)     = v0;
        *reinterpret_cast<float4*>(prow + (ull)i * NUM_OUT + 4) = v1;
    }
}

// out = p0 * p1 * p2 * p3 elementwise (float4-vectorized)
__global__ void combine_kernel(float* __restrict__ out) {
    int i = blockIdx.x * blockDim.x + threadIdx.x;
    if (i < (BATCH * NUM_OUT) / 4) {
        float4 a = reinterpret_cast<const float4*>(g_part[0])[i];
        float4 b = reinterpret_cast<const float4*>(g_part[1])[i];
        float4 c = reinterpret_cast<const float4*>(g_part[2])[i];
        float4 d = reinterpret_cast<const float4*>(g_part[3])[i];
        float4 v;
        v.x = (a.x * b.x) * (c.x * d.x);
        v.y = (a.y * b.y) * (c.y * d.y);
        v.z = (a.z * b.z) * (c.z * d.z);
        v.w = (a.w * b.w) * (c.w * d.w);
        reinterpret_cast<float4*>(out)[i] = v;
    }
}

extern "C" void kernel_launch(void* const* d_in, const int* in_sizes, int n_in,
                              void* d_out, int out_size) {
    const float* x    = (const float*)d_in[0];   // [2048, 512]
    const float* Wraw = (const float*)d_in[1];   // [256, 512]
    float* out        = (float*)d_out;           // [2048, 256]

    dim3 pgrid(NUM_OUT / 32, IN_DIM / 32);       // 8 x 16
    dim3 pblk(32, 8);
    precompute_kernel<<<pgrid, pblk>>>(Wraw);

    dim3 grid(BATCH / BM, NUM_OUT / BN, KSPLIT); // 32 x 2 x 4 = 256 CTAs
    logic_kernel<<<grid, NTHREADS>>>(x);

    combine_kernel<<<(BATCH * NUM_OUT / 4 + 255) / 256, 256>>>(out);
}